// round 1
// baseline (speedup 1.0000x reference)
#include <cuda_runtime.h>
#include <cstdint>

// Problem constants
#define BB   16
#define NN   8192
#define CIN  3
#define HID  64
#define DD   256
#define KK   4
#define GHID 128
#define DOUT 128
#define TILE 128
#define NTILES (NN / TILE)   // 64

// ---------------- device scratch (static, no allocations) ----------------
__device__ int      g_cnt[BB * KK];
__device__ int      g_idx[BB * KK * NN];       // per (b,k) index lists
__device__ unsigned g_maxu[BB * DD];           // flipped-float max slots

// ---------------- helpers ----------------
__device__ __forceinline__ float gelu_exact(float x) {
    return 0.5f * x * (1.0f + erff(x * 0.7071067811865476f));
}

__device__ __forceinline__ unsigned long long fma2(unsigned long long a,
                                                   unsigned long long b,
                                                   unsigned long long c) {
    unsigned long long d;
    asm("fma.rn.f32x2 %0, %1, %2, %3;" : "=l"(d) : "l"(a), "l"(b), "l"(c));
    return d;
}

__device__ __forceinline__ unsigned long long pack2(float lo, float hi) {
    unsigned long long r;
    asm("mov.b64 %0, {%1, %2};" : "=l"(r) : "f"(lo), "f"(hi));
    return r;
}

__device__ __forceinline__ void unpack2(unsigned long long v, float& lo, float& hi) {
    asm("mov.b64 {%0, %1}, %2;" : "=f"(lo), "=f"(hi) : "l"(v));
}

// order-preserving float -> uint mapping (for exact atomic max)
__device__ __forceinline__ unsigned flip_f32(float f) {
    unsigned u = __float_as_uint(f);
    return (u & 0x80000000u) ? ~u : (u | 0x80000000u);
}
__device__ __forceinline__ float unflip_f32(unsigned e) {
    unsigned u = (e & 0x80000000u) ? (e ^ 0x80000000u) : ~e;
    return __uint_as_float(u);
}

// ---------------- K0: reset scratch ----------------
__global__ void k0_init() {
    int t = threadIdx.x;
    if (t < BB * KK) g_cnt[t] = 0;
    for (int i = t; i < BB * DD; i += blockDim.x) g_maxu[i] = 0u;  // below all finite flips
}

// ---------------- K1: argmax classify + compaction ----------------
// grid: (B*N/256) blocks of 256; each block covers 256 consecutive n in one b.
__global__ void k1_classify(const float* __restrict__ lab) {
    __shared__ int scnt[KK];
    __shared__ int sbase[KK];
    int t   = threadIdx.x;
    int gid = blockIdx.x * 256 + t;
    int b   = gid / NN;
    int n   = gid % NN;

    if (t < KK) scnt[t] = 0;
    __syncthreads();

    const float* lb = lab + (size_t)b * KK * NN + n;
    float l0 = lb[0], l1 = lb[NN], l2 = lb[2 * NN], l3 = lb[3 * NN];
    int k = 0; float best = l0;
    if (l1 > best) { best = l1; k = 1; }
    if (l2 > best) { best = l2; k = 2; }
    if (l3 > best) { best = l3; k = 3; }

    int pos = atomicAdd(&scnt[k], 1);
    __syncthreads();
    if (t < KK) sbase[t] = atomicAdd(&g_cnt[b * KK + t], scnt[t]);
    __syncthreads();
    g_idx[(b * KK + k) * NN + sbase[k] + pos] = n;
}

// ---------------- K2: branch MLP + fused per-batch max ----------------
// grid: (NTILES, K, B), 256 threads. Thread = output dim d.
__global__ __launch_bounds__(256, 2)
void k2_main(const float* __restrict__ x,
             const float* __restrict__ W1, const float* __restrict__ b1,
             const float* __restrict__ W2, const float* __restrict__ b2) {
    __shared__ float sh_h[TILE * HID];   // 32 KB
    __shared__ float sh_x0[TILE], sh_x1[TILE], sh_x2[TILE];
    __shared__ int   sh_idx[TILE];
    __shared__ float sh_w1[CIN * HID];
    __shared__ float sh_b1[HID];

    const int tile = blockIdx.x, k = blockIdx.y, b = blockIdx.z;
    const int cnt = g_cnt[b * KK + k];
    const int start = tile * TILE;
    if (start >= cnt) return;
    const int npts = min(TILE, cnt - start);
    const int t = threadIdx.x;

    if (t < TILE && t < npts) sh_idx[t] = g_idx[(b * KK + k) * NN + start + t];
    if (t < CIN * HID)        sh_w1[t]  = W1[k * CIN * HID + t];
    if (t < HID)              sh_b1[t]  = b1[k * HID + t];
    __syncthreads();

    if (t < npts) {
        int n = sh_idx[t];
        const float* xb = x + (size_t)b * CIN * NN;
        sh_x0[t] = xb[n];
        sh_x1[t] = xb[NN + n];
        sh_x2[t] = xb[2 * NN + n];
    }
    __syncthreads();

    // phase 1: h = gelu(x @ W1 + b1); lane->j mapping keeps stores conflict-free
    {
        int j = t & (HID - 1);
        int g = t >> 6;                       // 0..3
        float w10 = sh_w1[j], w11 = sh_w1[HID + j], w12 = sh_w1[2 * HID + j];
        float bb  = sh_b1[j];
        for (int p = g; p < npts; p += 4) {
            float v = fmaf(sh_x0[p], w10, fmaf(sh_x1[p], w11, fmaf(sh_x2[p], w12, bb)));
            sh_h[p * HID + j] = gelu_exact(v);
        }
    }
    __syncthreads();

    // phase 2: thread = dim d; W2 column resident in 32 packed f32x2 registers
    const int d = t;
    const float* w2base = W2 + (size_t)(k * HID) * DD + d;
    unsigned long long w2p[HID / 2];
    #pragma unroll
    for (int i = 0; i < HID / 2; i++) {
        float lo = w2base[(2 * i) * DD];
        float hi = w2base[(2 * i + 1) * DD];
        w2p[i] = pack2(lo, hi);
    }
    const float b2d = b2[k * DD + d];

    float m = -3.402823466e38f;
    for (int p = 0; p < npts; p++) {
        const ulonglong2* hv = reinterpret_cast<const ulonglong2*>(sh_h + p * HID);
        unsigned long long a0 = 0ull, a1 = 0ull, a2 = 0ull, a3 = 0ull;
        #pragma unroll
        for (int q = 0; q < 16; q += 2) {
            ulonglong2 h0 = hv[q];
            ulonglong2 h1 = hv[q + 1];
            a0 = fma2(h0.x, w2p[2 * q],     a0);
            a1 = fma2(h0.y, w2p[2 * q + 1], a1);
            a2 = fma2(h1.x, w2p[2 * q + 2], a2);
            a3 = fma2(h1.y, w2p[2 * q + 3], a3);
        }
        float s0, s1, s2, s3, s4, s5, s6, s7;
        unpack2(a0, s0, s1); unpack2(a1, s2, s3);
        unpack2(a2, s4, s5); unpack2(a3, s6, s7);
        float f = (((s0 + s1) + (s2 + s3)) + ((s4 + s5) + (s6 + s7))) + b2d;
        m = fmaxf(m, f);
    }
    atomicMax(&g_maxu[b * DD + d], flip_f32(m));
}

// ---------------- K3: global MLP on per-batch max ----------------
// grid: B blocks of 128 threads; thread = output unit.
__global__ void k3_head(const float* __restrict__ Wg1, const float* __restrict__ bg1,
                        const float* __restrict__ Wg2, const float* __restrict__ bg2,
                        float* __restrict__ out) {
    __shared__ float sg[DD];
    __shared__ float shg[GHID];
    const int b = blockIdx.x;
    const int t = threadIdx.x;

    sg[t]          = unflip_f32(g_maxu[b * DD + t]);
    sg[t + GHID]   = unflip_f32(g_maxu[b * DD + t + GHID]);
    __syncthreads();

    float acc = bg1[t];
    #pragma unroll 8
    for (int j = 0; j < DD; j++) acc = fmaf(sg[j], Wg1[j * GHID + t], acc);
    shg[t] = gelu_exact(acc);
    __syncthreads();

    float acc2 = bg2[t];
    #pragma unroll 8
    for (int j = 0; j < GHID; j++) acc2 = fmaf(shg[j], Wg2[j * DOUT + t], acc2);
    out[b * DOUT + t] = acc2;
}

// ---------------- launch ----------------
extern "C" void kernel_launch(void* const* d_in, const int* in_sizes, int n_in,
                              void* d_out, int out_size) {
    const float* x     = (const float*)d_in[0];
    const float* xlab  = (const float*)d_in[1];
    const float* W1    = (const float*)d_in[2];
    const float* b1    = (const float*)d_in[3];
    const float* W2    = (const float*)d_in[4];
    const float* b2    = (const float*)d_in[5];
    const float* Wg1   = (const float*)d_in[6];
    const float* bg1   = (const float*)d_in[7];
    const float* Wg2   = (const float*)d_in[8];
    const float* bg2   = (const float*)d_in[9];
    float* out = (float*)d_out;

    k0_init<<<1, 256>>>();
    k1_classify<<<(BB * NN) / 256, 256>>>(xlab);
    k2_main<<<dim3(NTILES, KK, BB), 256>>>(x, W1, b1, W2, b2);
    k3_head<<<BB, GHID>>>(Wg1, bg1, Wg2, bg2, out);
}

// round 2
// speedup vs baseline: 1.0423x; 1.0423x over previous
#include <cuda_runtime.h>
#include <cstdint>

// Problem constants
#define BB   16
#define NN   8192
#define CIN  3
#define HID  64
#define DD   256
#define KK   4
#define GHID 128
#define DOUT 128
#define TILE 128
#define NTILES (NN / TILE)   // 64

// ---------------- device scratch (static, no allocations) ----------------
__device__ int      g_cnt[BB * KK];
__device__ int      g_idx[BB * KK * NN];       // per (b,k) index lists
__device__ unsigned g_maxu[BB * DD];           // flipped-float max slots

// ---------------- helpers ----------------
__device__ __forceinline__ float gelu_exact(float x) {
    return 0.5f * x * (1.0f + erff(x * 0.7071067811865476f));
}

__device__ __forceinline__ unsigned long long fma2(unsigned long long a,
                                                   unsigned long long b,
                                                   unsigned long long c) {
    unsigned long long d;
    asm("fma.rn.f32x2 %0, %1, %2, %3;" : "=l"(d) : "l"(a), "l"(b), "l"(c));
    return d;
}

__device__ __forceinline__ unsigned long long add2(unsigned long long a,
                                                   unsigned long long b) {
    unsigned long long d;
    asm("add.rn.f32x2 %0, %1, %2;" : "=l"(d) : "l"(a), "l"(b));
    return d;
}

__device__ __forceinline__ unsigned long long pack2(float lo, float hi) {
    unsigned long long r;
    asm("mov.b64 %0, {%1, %2};" : "=l"(r) : "f"(lo), "f"(hi));
    return r;
}

__device__ __forceinline__ void unpack2(unsigned long long v, float& lo, float& hi) {
    asm("mov.b64 {%0, %1}, %2;" : "=f"(lo), "=f"(hi) : "l"(v));
}

// order-preserving float -> uint mapping (for exact atomic max)
__device__ __forceinline__ unsigned flip_f32(float f) {
    unsigned u = __float_as_uint(f);
    return (u & 0x80000000u) ? ~u : (u | 0x80000000u);
}
__device__ __forceinline__ float unflip_f32(unsigned e) {
    unsigned u = (e & 0x80000000u) ? (e ^ 0x80000000u) : ~e;
    return __uint_as_float(u);
}

// ---------------- K0: reset scratch (wide grid, one pass) ----------------
__global__ void k0_init() {
    int i = blockIdx.x * 256 + threadIdx.x;
    if (i < BB * KK) g_cnt[i] = 0;
    if (i < BB * DD) g_maxu[i] = 0u;   // below all finite flipped floats
}

// ---------------- K1: argmax classify + compaction ----------------
// grid: (B*N/256) blocks of 256; each block covers 256 consecutive n in one b.
__global__ void k1_classify(const float* __restrict__ lab) {
    __shared__ int scnt[KK];
    __shared__ int sbase[KK];
    int t   = threadIdx.x;
    int gid = blockIdx.x * 256 + t;
    int b   = gid / NN;
    int n   = gid % NN;

    if (t < KK) scnt[t] = 0;
    __syncthreads();

    const float* lb = lab + (size_t)b * KK * NN + n;
    float l0 = lb[0], l1 = lb[NN], l2 = lb[2 * NN], l3 = lb[3 * NN];
    int k = 0; float best = l0;
    if (l1 > best) { best = l1; k = 1; }
    if (l2 > best) { best = l2; k = 2; }
    if (l3 > best) { best = l3; k = 3; }

    int pos = atomicAdd(&scnt[k], 1);
    __syncthreads();
    if (t < KK) sbase[t] = atomicAdd(&g_cnt[b * KK + t], scnt[t]);
    __syncthreads();
    g_idx[(b * KK + k) * NN + sbase[k] + pos] = n;
}

// ---------------- K2: branch MLP + fused per-batch max ----------------
// grid: (NTILES, K, B), 256 threads. Thread = output dim d.
__global__ __launch_bounds__(256, 2)
void k2_main(const float* __restrict__ x,
             const float* __restrict__ W1, const float* __restrict__ b1,
             const float* __restrict__ W2, const float* __restrict__ b2) {
    __shared__ float sh_h[TILE * HID];   // 32 KB
    __shared__ float sh_x0[TILE], sh_x1[TILE], sh_x2[TILE];
    __shared__ int   sh_idx[TILE];
    __shared__ float sh_w1[CIN * HID];
    __shared__ float sh_b1[HID];

    const int tile = blockIdx.x, k = blockIdx.y, b = blockIdx.z;
    const int cnt = g_cnt[b * KK + k];
    const int start = tile * TILE;
    if (start >= cnt) return;
    const int npts = min(TILE, cnt - start);
    const int t = threadIdx.x;

    if (t < TILE && t < npts) sh_idx[t] = g_idx[(b * KK + k) * NN + start + t];
    if (t < CIN * HID)        sh_w1[t]  = W1[k * CIN * HID + t];
    if (t < HID)              sh_b1[t]  = b1[k * HID + t];
    __syncthreads();

    if (t < npts) {
        int n = sh_idx[t];
        const float* xb = x + (size_t)b * CIN * NN;
        sh_x0[t] = xb[n];
        sh_x1[t] = xb[NN + n];
        sh_x2[t] = xb[2 * NN + n];
    }
    __syncthreads();

    // phase 1: h = gelu(x @ W1 + b1); lane->j mapping keeps stores conflict-free
    {
        int j = t & (HID - 1);
        int g = t >> 6;                       // 0..3
        float w10 = sh_w1[j], w11 = sh_w1[HID + j], w12 = sh_w1[2 * HID + j];
        float bb  = sh_b1[j];
        for (int p = g; p < npts; p += 4) {
            float v = fmaf(sh_x0[p], w10, fmaf(sh_x1[p], w11, fmaf(sh_x2[p], w12, bb)));
            sh_h[p * HID + j] = gelu_exact(v);
        }
    }
    __syncthreads();

    // phase 2: thread = dim d; W2 column resident in 32 packed f32x2 registers
    const int d = t;
    const float* w2base = W2 + (size_t)(k * HID) * DD + d;
    unsigned long long w2p[HID / 2];
    #pragma unroll
    for (int i = 0; i < HID / 2; i++) {
        float lo = w2base[(2 * i) * DD];
        float hi = w2base[(2 * i + 1) * DD];
        w2p[i] = pack2(lo, hi);
    }

    // bias hoisted out of the max loop: max(s + b2d) = max(s) + b2d
    float m = -3.402823466e38f;
    #pragma unroll 2
    for (int p = 0; p < npts; p++) {
        const ulonglong2* hv = reinterpret_cast<const ulonglong2*>(sh_h + p * HID);
        unsigned long long a0 = 0ull, a1 = 0ull, a2 = 0ull, a3 = 0ull;
        #pragma unroll
        for (int q = 0; q < 16; q += 2) {
            ulonglong2 h0 = hv[q];
            ulonglong2 h1 = hv[q + 1];
            a0 = fma2(h0.x, w2p[2 * q],     a0);
            a1 = fma2(h0.y, w2p[2 * q + 1], a1);
            a2 = fma2(h1.x, w2p[2 * q + 2], a2);
            a3 = fma2(h1.y, w2p[2 * q + 3], a3);
        }
        // packed tree-reduce: 3 f32x2 adds, then one scalar add
        unsigned long long s = add2(add2(a0, a1), add2(a2, a3));
        float lo, hi; unpack2(s, lo, hi);
        m = fmaxf(m, lo + hi);
    }
    m += b2[k * DD + d];
    atomicMax(&g_maxu[b * DD + d], flip_f32(m));
}

// ---------------- K3: global MLP on per-batch max ----------------
// grid: B blocks of 512 threads; 4-way split over the j (reduction) axis
// so the weight-load latency is hidden by 4x the outstanding loads.
__global__ __launch_bounds__(512, 1)
void k3_head(const float* __restrict__ Wg1, const float* __restrict__ bg1,
             const float* __restrict__ Wg2, const float* __restrict__ bg2,
             float* __restrict__ out) {
    __shared__ float sg[DD];
    __shared__ float part[512];
    __shared__ float shg[GHID];
    const int b   = blockIdx.x;
    const int tid = threadIdx.x;
    const int t   = tid & 127;     // output unit
    const int g   = tid >> 7;      // j-split group 0..3

    if (tid < DD) sg[tid] = unflip_f32(g_maxu[b * DD + tid]);
    __syncthreads();

    // layer 1: 256 -> 128, each thread covers 64 j's
    {
        float acc = 0.0f;
        const int j0 = g * 64;
        #pragma unroll 16
        for (int j = 0; j < 64; j++)
            acc = fmaf(sg[j0 + j], Wg1[(j0 + j) * GHID + t], acc);
        part[tid] = acc;
    }
    __syncthreads();
    if (tid < GHID) {
        float v = part[tid] + part[tid + 128] + part[tid + 256] + part[tid + 384] + bg1[tid];
        shg[tid] = gelu_exact(v);
    }
    __syncthreads();

    // layer 2: 128 -> 128, each thread covers 32 j's
    {
        float acc = 0.0f;
        const int j0 = g * 32;
        #pragma unroll 16
        for (int j = 0; j < 32; j++)
            acc = fmaf(shg[j0 + j], Wg2[(j0 + j) * DOUT + t], acc);
        part[tid] = acc;
    }
    __syncthreads();
    if (tid < DOUT)
        out[b * DOUT + tid] = part[tid] + part[tid + 128] + part[tid + 256] + part[tid + 384] + bg2[tid];
}

// ---------------- launch ----------------
extern "C" void kernel_launch(void* const* d_in, const int* in_sizes, int n_in,
                              void* d_out, int out_size) {
    const float* x     = (const float*)d_in[0];
    const float* xlab  = (const float*)d_in[1];
    const float* W1    = (const float*)d_in[2];
    const float* b1    = (const float*)d_in[3];
    const float* W2    = (const float*)d_in[4];
    const float* b2    = (const float*)d_in[5];
    const float* Wg1   = (const float*)d_in[6];
    const float* bg1   = (const float*)d_in[7];
    const float* Wg2   = (const float*)d_in[8];
    const float* bg2   = (const float*)d_in[9];
    float* out = (float*)d_out;

    k0_init<<<(BB * DD + 255) / 256, 256>>>();
    k1_classify<<<(BB * NN) / 256, 256>>>(xlab);
    k2_main<<<dim3(NTILES, KK, BB), 256>>>(x, W1, b1, W2, b2);
    k3_head<<<BB, 512>>>(Wg1, bg1, Wg2, bg2, out);
}